// round 3
// baseline (speedup 1.0000x reference)
#include <cuda_runtime.h>
#include <cstdint>

// VectorQuantizer: z_e (64,64,64,64) f32, emb (512,64) f32.
// M = 262144 points, D = 64, K = 512.
// Output (f32): [ z_q (N,D,H,W) : 16777216 ][ vq_loss : 1 ][ indices (N,H,W) : 262144 ]

#define KCODES   512
#define DDIM     64
#define HW       4096
#define DHW      262144
#define NPTS     262144
#define EROW     64              // unpadded: all argmin LDS are warp-broadcast
#define ZQ_OFF   0
#define LOSS_OFF 16777216
#define IDX_OFF  16777217

#define NBLOCKS  148
#define NTHREADS 512
#define NWARPS_B (NTHREADS / 32)          // 16
#define TOTWARPS (NBLOCKS * NWARPS_B)     // 2368
#define NTILES   (NPTS / 32)              // 8192 (tiles of 32 points, 1 per lane)

__device__ float g_partials[NBLOCKS];
__device__ int   g_counter = 0;

__device__ __forceinline__ uint64_t pk2(float lo, float hi) {
    uint64_t r;
    asm("mov.b64 %0, {%1, %2};" : "=l"(r) : "f"(lo), "f"(hi));
    return r;
}
__device__ __forceinline__ float2 upk2(uint64_t v) {
    float2 r;
    asm("mov.b64 {%0, %1}, %2;" : "=f"(r.x), "=f"(r.y) : "l"(v));
    return r;
}
__device__ __forceinline__ void ffma2(uint64_t& d, uint64_t a, uint64_t b) {
    asm("fma.rn.f32x2 %0, %1, %2, %0;" : "+l"(d) : "l"(a), "l"(b));
}
__device__ __forceinline__ uint64_t fadd2(uint64_t a, uint64_t b) {
    uint64_t r;
    asm("add.rn.f32x2 %0, %1, %2;" : "=l"(r) : "l"(a), "l"(b));
    return r;
}

extern "C" __global__ void __launch_bounds__(NTHREADS, 1)
vq_kernel(const float* __restrict__ z, const float* __restrict__ emb,
          float* __restrict__ out)
{
    extern __shared__ float smem[];
    float*  se    = smem;                              // KCODES*EROW floats (128KB)
    float*  sesq  = smem + KCODES * EROW;              // KCODES floats
    float*  sred  = sesq + KCODES;                     // NWARPS_B floats
    double* sdbl  = (double*)(sred + NWARPS_B + 2);    // 256 doubles (final reduce)
    int*    sflag = (int*)(sdbl + 256);

    const int tid  = threadIdx.x;
    const int wib  = tid >> 5;
    const int lane = tid & 31;

    // ---- codebook -> smem, coalesced float4 ----
    {
        const float4* e4 = (const float4*)emb;          // 8192 float4
        #pragma unroll
        for (int i = tid; i < KCODES * (DDIM / 4); i += NTHREADS)
            *(((float4*)se) + i) = e4[i];
    }
    __syncthreads();

    // ---- e_sq per code ----
    for (int k = tid; k < KCODES; k += NTHREADS) {
        const float* r = se + k * EROW;
        float s = 0.f;
        #pragma unroll
        for (int d = 0; d < DDIM; d++) s = fmaf(r[d], r[d], s);
        sesq[k] = s;
    }
    __syncthreads();

    // ---- digit-swapped persistent warp->tile assignment ----
    // vwarp = wib*NBLOCKS + bid spreads the "extra tile" warps evenly over SMs.
    const int vwarp = wib * NBLOCKS + blockIdx.x;

    float ls = 0.f;  // per-thread loss accumulator

    for (int t = vwarp; t < NTILES; t += TOTWARPS) {
        const int p  = t * 32 + lane;       // tiles never straddle an n boundary
        const int n  = p >> 12;
        const int hw = p & (HW - 1);
        const float* zb = z + (size_t)n * DHW + hw;

        uint64_t zp[DDIM / 2];
        float zsq = 0.f;
        #pragma unroll
        for (int d = 0; d < DDIM; d += 2) {
            float a = zb[(size_t)d * HW];
            float b = zb[(size_t)(d + 1) * HW];
            zsq = fmaf(a, a, zsq);
            zsq = fmaf(b, b, zsq);
            zp[d >> 1] = pk2(a, b);
        }

        // ---- argmin over K: dist = (z_sq + e_sq[k]) - 2*dot (ref rounding) ----
        float best = 3.4e38f;
        int   bidx = 0;
        for (int k = 0; k < KCODES; k++) {
            const ulonglong2* e2 = (const ulonglong2*)(se + k * EROW);
            uint64_t a0 = 0ull, a1 = 0ull;
            #pragma unroll
            for (int j = 0; j < 16; j++) {
                ulonglong2 ee = e2[j];
                ffma2(a0, zp[2 * j],     ee.x);
                ffma2(a1, zp[2 * j + 1], ee.y);
            }
            float2 s = upk2(fadd2(a0, a1));
            float dist = fmaf(-2.0f, s.x + s.y, zsq + sesq[k]);
            bool m = dist < best;
            best = m ? dist : best;
            bidx = m ? k : bidx;
        }

        // ---- epilogue: gather z_q, write, accumulate loss ----
        const float* eb = se + bidx * EROW;
        float* op = out + ZQ_OFF + (size_t)n * DHW + hw;
        #pragma unroll
        for (int d = 0; d < DDIM; d += 2) {
            float2 zz = upk2(zp[d >> 1]);
            float v0 = eb[d], v1 = eb[d + 1];
            op[(size_t)d * HW]       = v0;
            op[(size_t)(d + 1) * HW] = v1;
            float d0 = zz.x - v0, d1 = zz.y - v1;
            ls = fmaf(d0, d0, ls);
            ls = fmaf(d1, d1, ls);
        }
        out[IDX_OFF + p] = (float)bidx;
    }

    // ---- block-reduce loss (deterministic fixed order) ----
    #pragma unroll
    for (int off = 16; off > 0; off >>= 1)
        ls += __shfl_down_sync(0xFFFFFFFFu, ls, off);
    if (lane == 0) sred[wib] = ls;
    __syncthreads();
    if (tid == 0) {
        float s = 0.f;
        #pragma unroll
        for (int w = 0; w < NWARPS_B; w++) s += sred[w];
        g_partials[blockIdx.x] = s;
        __threadfence();
        int prev = atomicAdd(&g_counter, 1);
        *sflag = (prev == NBLOCKS - 1);
    }
    __syncthreads();

    // ---- last block: final reduction (deterministic tree), counter reset ----
    if (*sflag) {
        double v = 0.0;
        if (tid < NBLOCKS) v = (double)g_partials[tid];
        if (tid < 256) sdbl[tid] = v;
        __syncthreads();
        #pragma unroll
        for (int off = 128; off > 0; off >>= 1) {
            if (tid < off) sdbl[tid] += sdbl[tid + off];
            __syncthreads();
        }
        if (tid == 0) {
            out[LOSS_OFF] = (float)(sdbl[0] / 16777216.0);  // mean over M*D
            g_counter = 0;                                   // replay-safe reset
        }
    }
}

extern "C" void kernel_launch(void* const* d_in, const int* in_sizes, int n_in,
                              void* d_out, int out_size)
{
    const float* z   = (const float*)d_in[0];
    const float* emb = (const float*)d_in[1];
    if (n_in >= 2 && in_sizes[0] < in_sizes[1]) {
        const float* t = z; z = emb; emb = t;
    }
    float* out = (float*)d_out;

    const int smem_bytes = (KCODES * EROW + KCODES + NWARPS_B + 2) * (int)sizeof(float)
                         + 256 * (int)sizeof(double) + 16;
    static bool attr_set = false;
    if (!attr_set) {
        cudaFuncSetAttribute(vq_kernel, cudaFuncAttributeMaxDynamicSharedMemorySize,
                             smem_bytes);
        attr_set = true;
    }

    vq_kernel<<<NBLOCKS, NTHREADS, smem_bytes>>>(z, emb, out);
}